// round 11
// baseline (speedup 1.0000x reference)
#include <cuda_runtime.h>
#include <stdint.h>

// BATCH=128, BUFFER_SIZE=16, IMG4 = 128*128*3/4 = 12288 float4 per image.
// out[m] = combined[m/16 + 1 + m%16], combined = concat(buffer[16], inputs[128]).
//
// Inverted (scatter) form: source combined[j] (j in 1..143) lands at output
// images m = 16*(j-1) - 15*k for k in [max(0,j-128), min(15,j-1)].
// Load each source float4 ONCE, store it to all destinations (up to 16).
// This cuts load traffic 16x (450MB -> 28MB) leaving a pure write stream.

#define KBUF 16
#define IMG4 12288
#define CHUNK4 1024   // float4 per block (12 chunks per image)

__global__ __launch_bounds__(256) void image_buffer_scatter(
    const float4* __restrict__ inputs,   // [128, IMG4]
    const float4* __restrict__ buffer,   // [16,  IMG4]
    float4* __restrict__ out)            // [2048, IMG4]
{
    const int j = blockIdx.y + 1;        // combined index, 1..143 (block-uniform)

    const float4* __restrict__ srcimg = (j < KBUF)
        ? (buffer + j * IMG4)
        : (inputs + (j - KBUF) * IMG4);

    const int base = blockIdx.x * CHUNK4 + threadIdx.x;   // 256 thr * 4 = 1024 ✓

    // Load once (4 independent float4; L2-resident after the cold miss).
    const float4 v0 = srcimg[base + 0 * 256];
    const float4 v1 = srcimg[base + 1 * 256];
    const float4 v2 = srcimg[base + 2 * 256];
    const float4 v3 = srcimg[base + 3 * 256];

    const int k_lo = (j - 128 > 0) ? (j - 128) : 0;
    const int k_hi = (j - 1 < 15) ? (j - 1) : 15;

    // Destination image m = 16*(j-1) - 15*k; step -15*IMG4 per k.
    int64_t doff = (int64_t)(16 * (j - 1) - 15 * k_lo) * IMG4 + base;
    #pragma unroll 4
    for (int k = k_lo; k <= k_hi; ++k) {
        float4* __restrict__ dst = out + doff;
        __stcs(dst + 0 * 256, v0);
        __stcs(dst + 1 * 256, v1);
        __stcs(dst + 2 * 256, v2);
        __stcs(dst + 3 * 256, v3);
        doff -= (int64_t)15 * IMG4;
    }
}

extern "C" void kernel_launch(void* const* d_in, const int* in_sizes, int n_in,
                              void* d_out, int out_size) {
    const float4* inputs = (const float4*)d_in[0];
    const float4* buffer = (const float4*)d_in[1];
    float4* out = (float4*)d_out;

    dim3 grid(IMG4 / CHUNK4, 143);   // 12 chunks x 143 source images
    image_buffer_scatter<<<grid, 256>>>(inputs, buffer, out);
}